// round 14
// baseline (speedup 1.0000x reference)
#include <cuda_runtime.h>
#include <cuda_bf16.h>
#include <cstdint>

#define T_TOKENS 2048
#define DIM_     2048
#define HID_     5632
#define NEXP     8
#define NENT     (T_TOKENS * 2)

// ---------------------------------------------------------------------------
// Scratch (device globals — no cudaMalloc allowed)
// ---------------------------------------------------------------------------
__device__ int   g_eid [T_TOKENS][2];
__device__ float g_ew  [T_TOKENS][2];
__device__ int   g_pos [T_TOKENS][2];
__device__ int   g_list[NEXP][T_TOKENS];
__device__ int   g_cnt [NEXP];
__device__ int   g_off [NEXP];
__device__ __nv_bfloat16 g_xhi[(size_t)T_TOKENS * DIM_];
__device__ __nv_bfloat16 g_xlo[(size_t)T_TOKENS * DIM_];
__device__ __nv_bfloat16 g_hh [(size_t)NENT * HID_];
__device__ __nv_bfloat16 g_hl [(size_t)NENT * HID_];
__device__ float         g_y  [(size_t)NENT * DIM_];

// ---------------------------------------------------------------------------
// Helpers
// ---------------------------------------------------------------------------
__device__ __forceinline__ uint32_t smem_u32(const void* p) {
    uint32_t a;
    asm("{ .reg .u64 t; cvta.to.shared.u64 t, %1; cvt.u32.u64 %0, t; }" : "=r"(a) : "l"(p));
    return a;
}
__device__ __forceinline__ uint32_t pkbf(__nv_bfloat16 a, __nv_bfloat16 b) {
    return (uint32_t)__bfloat16_as_ushort(a) | ((uint32_t)__bfloat16_as_ushort(b) << 16);
}
__device__ __forceinline__ void split_pair(float f0, float f1, uint32_t& hp, uint32_t& lp) {
    __nv_bfloat16 h0 = __float2bfloat16(f0);
    __nv_bfloat16 h1 = __float2bfloat16(f1);
    __nv_bfloat16 l0 = __float2bfloat16(f0 - __bfloat162float(h0));
    __nv_bfloat16 l1 = __float2bfloat16(f1 - __bfloat162float(h1));
    hp = pkbf(h0, h1);
    lp = pkbf(l0, l1);
}

#define LDM_X4(r, addr)                                                          \
    asm volatile("ldmatrix.sync.aligned.m8n8.x4.shared.b16 {%0,%1,%2,%3}, [%4];" \
        : "=r"((r)[0]), "=r"((r)[1]), "=r"((r)[2]), "=r"((r)[3]) : "r"(addr))

#define MMA_BF16(d, a, b0, b1)                                                   \
    asm volatile("mma.sync.aligned.m16n8k16.row.col.f32.bf16.bf16.f32 "          \
        "{%0,%1,%2,%3}, {%4,%5,%6,%7}, {%8,%9}, {%0,%1,%2,%3};"                  \
        : "+f"((d)[0]), "+f"((d)[1]), "+f"((d)[2]), "+f"((d)[3])                 \
        : "r"((a)[0]), "r"((a)[1]), "r"((a)[2]), "r"((a)[3]), "r"(b0), "r"(b1))

#define CP_ASYNC16(dst, src)                                                     \
    asm volatile("cp.async.cg.shared.global [%0], [%1], 16;" :: "r"(dst), "l"(src))
#define CP_COMMIT() asm volatile("cp.async.commit_group;" ::: "memory")
#define CP_WAIT0()  asm volatile("cp.async.wait_group 0;" ::: "memory")

// bf16 tiles: rows of 32 bf16 padded to 80B -> conflict-free ldmatrix (R4-R9)
#define ROWB     80
#define TILE_A   10240          // 128 rows * 80B (one A matrix: hi or lo)
#define OFF_AH   0
#define OFF_AL   10240
#define OFF_BH   20480          // B: 128 rows * 80B per matrix
#define OFF_BL   30720
#define STAGE_B  40960
#define SMEM_TOT (2 * STAGE_B)  // 81920; 2 CTAs/SM

#define NTHREADS 320            // 8 compute warps + 2 producer warps

// ---------------------------------------------------------------------------
// Gating + routing + x split
// ---------------------------------------------------------------------------
__global__ void gate_kernel(const float* __restrict__ x, const float* __restrict__ gw) {
    const int t = blockIdx.x, lane = threadIdx.x & 31, w = threadIdx.x >> 5;
    const float* xr = x + (size_t)t * DIM_;
    const float* gr = gw + (size_t)w * DIM_;
    float s = 0.f;
    for (int d = lane * 4; d < DIM_; d += 128) {
        float4 a = *(const float4*)(xr + d);
        float4 b = *(const float4*)(gr + d);
        s += a.x * b.x + a.y * b.y + a.z * b.z + a.w * b.w;
    }
    #pragma unroll
    for (int o = 16; o; o >>= 1) s += __shfl_xor_sync(0xffffffffu, s, o);
    __shared__ float sc[NEXP];
    if (lane == 0) sc[w] = s;
    __syncthreads();
    if (threadIdx.x == 0) {
        int b0 = 0; float s0 = sc[0];
        #pragma unroll
        for (int e = 1; e < NEXP; e++) if (sc[e] > s0) { s0 = sc[e]; b0 = e; }
        int b1 = -1; float s1 = -1e30f;
        #pragma unroll
        for (int e = 0; e < NEXP; e++) if (e != b0 && sc[e] > s1) { s1 = sc[e]; b1 = e; }
        float e1 = __expf(s1 - s0);
        float inv = 1.f / (1.f + e1);
        g_eid[t][0] = b0; g_eid[t][1] = b1;
        g_ew [t][0] = inv; g_ew [t][1] = e1 * inv;
    }
}

__global__ void route_kernel() {
    const int lane = threadIdx.x & 31, e = threadIdx.x >> 5;
    if (e < NEXP) {
        int cnt = 0;
        for (int t0 = 0; t0 < T_TOKENS; t0 += 32) {
            int t = t0 + lane;
            int e0 = g_eid[t][0], e1 = g_eid[t][1];
            bool sel = (e0 == e) || (e1 == e);
            int slot = (e0 == e) ? 0 : 1;
            unsigned m = __ballot_sync(0xffffffffu, sel);
            if (sel) {
                int p = cnt + __popc(m & ((1u << lane) - 1u));
                g_list[e][p] = t;
                g_pos[t][slot] = p;
            }
            cnt += __popc(m);
        }
        if (lane == 0) g_cnt[e] = cnt;
    }
    __syncthreads();
    if (threadIdx.x == 0) {
        int off = 0;
        #pragma unroll
        for (int i = 0; i < NEXP; i++) { g_off[i] = off; off += g_cnt[i]; }
    }
}

__global__ void split_x_kernel(const float* __restrict__ x) {
    int i = blockIdx.x * blockDim.x + threadIdx.x;
    float4 v = ((const float4*)x)[i];
    size_t o = (size_t)i * 4;
    float vv[4] = {v.x, v.y, v.z, v.w};
    #pragma unroll
    for (int k = 0; k < 4; k++) {
        __nv_bfloat16 h = __float2bfloat16(vv[k]);
        g_xhi[o + k] = h;
        g_xlo[o + k] = __float2bfloat16(vv[k] - __bfloat162float(h));
    }
}

// ---------------------------------------------------------------------------
// Producer fill helpers: recompute all state per call (no loop-carried regs).
// 64 producer threads (ptid 0..63) fill one BK=32 stage:
//   A: 16 cp.async chunks each (2 mats x 128 rows x 4 kq = 1024)
//   B: 8 tasks each (128 interleaved rows x 4 k-blocks = 512): 8 LDG + split + 2 STS
// ---------------------------------------------------------------------------
__device__ __forceinline__ void fill_stage_ffn1(
    char* st, uint32_t stS, int ptid, int e, int cnt, int m0, int n0, int kk,
    const float* w1e, const float* w3e)
{
    const int rq = ptid >> 2, kq = ptid & 3;
    // A chunks
    #pragma unroll
    for (int q = 0; q < 8; q++) {
        int row = q * 16 + rq;
        int tok = g_list[e][min(m0 + row, cnt - 1)];
        uint32_t dof = row * ROWB + kq * 16;
        CP_ASYNC16(stS + OFF_AH + dof, g_xhi + (size_t)tok * DIM_ + kq * 8 + kk);
        CP_ASYNC16(stS + OFF_AL + dof, g_xlo + (size_t)tok * DIM_ + kq * 8 + kk);
    }
    // B tasks
    const float* mb = (ptid & 1) ? w3e : w1e;
    #pragma unroll
    for (int r = 0; r < 8; r++) {
        int np = ptid + (r & 1) * 64;
        int kb = r >> 1;
        const float* src = mb + (size_t)(kk + kb * 8) * HID_ + n0 + ((ptid >> 1) + (r & 1) * 32);
        float f[8];
        #pragma unroll
        for (int j = 0; j < 8; j++) f[j] = src[(size_t)j * HID_];
        uint32_t hp[4], lp[4];
        #pragma unroll
        for (int j = 0; j < 4; j++) split_pair(f[2*j], f[2*j+1], hp[j], lp[j]);
        uint32_t bo = np * ROWB + kb * 16;
        *(uint4*)(st + OFF_BH + bo) = make_uint4(hp[0], hp[1], hp[2], hp[3]);
        *(uint4*)(st + OFF_BL + bo) = make_uint4(lp[0], lp[1], lp[2], lp[3]);
    }
    CP_COMMIT();
}

__device__ __forceinline__ void fill_stage_ffn2(
    char* st, uint32_t stS, int ptid, int e, int cnt, int m0, int n0, int kk,
    const float* w2e, int base)
{
    const int rq = ptid >> 2, kq = ptid & 3;
    #pragma unroll
    for (int q = 0; q < 8; q++) {
        int row = q * 16 + rq;
        int r = base + min(m0 + row, cnt - 1);
        uint32_t dof = row * ROWB + kq * 16;
        CP_ASYNC16(stS + OFF_AH + dof, g_hh + (size_t)r * HID_ + kq * 8 + kk);
        CP_ASYNC16(stS + OFF_AL + dof, g_hl + (size_t)r * HID_ + kq * 8 + kk);
    }
    #pragma unroll
    for (int r = 0; r < 8; r++) {
        int np = ptid + (r & 1) * 64;
        int kb = r >> 1;
        const float* src = w2e + (size_t)(kk + kb * 8) * DIM_ + n0 + np;
        float f[8];
        #pragma unroll
        for (int j = 0; j < 8; j++) f[j] = src[(size_t)j * DIM_];
        uint32_t hp[4], lp[4];
        #pragma unroll
        for (int j = 0; j < 4; j++) split_pair(f[2*j], f[2*j+1], hp[j], lp[j]);
        uint32_t bo = np * ROWB + kb * 16;
        *(uint4*)(st + OFF_BH + bo) = make_uint4(hp[0], hp[1], hp[2], hp[3]);
        *(uint4*)(st + OFF_BL + bo) = make_uint4(lp[0], lp[1], lp[2], lp[3]);
    }
    CP_COMMIT();
}

// ---------------------------------------------------------------------------
// GEMM1: u = x@w1, v = x@w3 (3-term bf16 split), h = silu(u)*v
// 320 threads: warps 0-7 compute (2m x 4n, warp tile 64x32, CTA 128 x 64 h),
// warps 8-9 produce (cp.async A + LDG/convert/STS B). One barrier/iter.
// ---------------------------------------------------------------------------
__global__ void __launch_bounds__(NTHREADS, 2) ffn1_kernel(const float* __restrict__ w1,
                                                           const float* __restrict__ w3) {
    const int e   = blockIdx.z;
    const int cnt = g_cnt[e];
    const int m0  = blockIdx.x * 128;
    if (m0 >= cnt) return;
    const int n0   = blockIdx.y * 64;     // h-cols
    const int base = g_off[e];

    extern __shared__ char sm[];
    const uint32_t sbase = smem_u32(sm);
    const int tid = threadIdx.x, lane = tid & 31, wid = tid >> 5;
    const bool is_comp = (wid < 8);
    const int wm = wid & 1, wn = (wid >> 1) & 3;
    const int ptid = tid & 63;

    const float* w1e = w1 + (size_t)e * DIM_ * HID_;
    const float* w3e = w3 + (size_t)e * DIM_ * HID_;

    const int mi = lane >> 3, lr = lane & 7;
    const uint32_t aLB = (uint32_t)((wm * 64 + (mi & 1) * 8 + lr) * ROWB + (mi >> 1) * 16);
    const uint32_t bLB = (uint32_t)((wn * 32 + (mi >> 1) * 8 + lr) * ROWB + (mi & 1) * 16);

    float acc[4][4][4];
    #pragma unroll
    for (int a = 0; a < 4; a++)
        #pragma unroll
        for (int b = 0; b < 4; b++)
            #pragma unroll
            for (int c = 0; c < 4; c++) acc[a][b][c] = 0.f;

    const int NCH = DIM_ / 32;   // 64
    // prologue: producers fill stage 0
    if (!is_comp) {
        fill_stage_ffn1(sm, sbase, ptid, e, cnt, m0, n0, 0, w1e, w3e);
        CP_WAIT0();
    }
    __syncthreads();

    for (int i = 0; i < NCH; i++) {
        const int s = i & 1;
        const uint32_t stS = sbase + s * STAGE_B;
        if (is_comp) {
            #pragma unroll
            for (int ks = 0; ks < 2; ks++) {
                uint32_t bh[2][4], bl[2][4];
                #pragma unroll
                for (int ng = 0; ng < 2; ng++) {
                    LDM_X4(bh[ng], stS + OFF_BH + bLB + ng * (16 * ROWB) + ks * 32);
                    LDM_X4(bl[ng], stS + OFF_BL + bLB + ng * (16 * ROWB) + ks * 32);
                }
                #pragma unroll
                for (int mt = 0; mt < 4; mt++) {
                    uint32_t ah[4], al[4];
                    LDM_X4(ah, stS + OFF_AH + aLB + mt * (16 * ROWB) + ks * 32);
                    LDM_X4(al, stS + OFF_AL + aLB + mt * (16 * ROWB) + ks * 32);
                    #pragma unroll
                    for (int ng = 0; ng < 2; ng++)
                        #pragma unroll
                        for (int h2 = 0; h2 < 2; h2++) {
                            int nt = ng * 2 + h2;
                            MMA_BF16(acc[mt][nt], ah, bh[ng][2*h2], bh[ng][2*h2+1]);
                            MMA_BF16(acc[mt][nt], al, bh[ng][2*h2], bh[ng][2*h2+1]);
                            MMA_BF16(acc[mt][nt], ah, bl[ng][2*h2], bl[ng][2*h2+1]);
                        }
                }
            }
        } else {
            if (i + 1 < NCH) {
                fill_stage_ffn1(sm + (1 - s) * STAGE_B, sbase + (1 - s) * STAGE_B,
                                ptid, e, cnt, m0, n0, (i + 1) * 32, w1e, w3e);
                CP_WAIT0();
            }
        }
        __syncthreads();
    }

    // epilogue: compute warps only; d0=u, d1=v for same h-col, SwiGLU in regs
    if (is_comp) {
        #pragma unroll
        for (int mt = 0; mt < 4; mt++)
            #pragma unroll
            for (int nt = 0; nt < 4; nt++) {
                int j = wn * 16 + nt * 4 + (lane & 3);
                #pragma unroll
                for (int rr = 0; rr < 2; rr++) {
                    int r  = wm * 64 + mt * 16 + (lane >> 2) + rr * 8;
                    int gm = m0 + r;
                    float u = acc[mt][nt][2*rr], v = acc[mt][nt][2*rr+1];
                    float h = u / (1.f + __expf(-u)) * v;
                    __nv_bfloat16 hh = __float2bfloat16(h);
                    __nv_bfloat16 hl = __float2bfloat16(h - __bfloat162float(hh));
                    if (gm < cnt) {
                        size_t dst = (size_t)(base + gm) * HID_ + n0 + j;
                        g_hh[dst] = hh;
                        g_hl[dst] = hl;
                    }
                }
            }
    }
}

// ---------------------------------------------------------------------------
// GEMM2: y = h @ w2 (3-term split). Same specialization; CTA 128 x 128.
// ---------------------------------------------------------------------------
__global__ void __launch_bounds__(NTHREADS, 2) ffn2_kernel(const float* __restrict__ w2) {
    const int e   = blockIdx.z;
    const int cnt = g_cnt[e];
    const int m0  = blockIdx.x * 128;
    if (m0 >= cnt) return;
    const int n0   = blockIdx.y * 128;
    const int base = g_off[e];

    extern __shared__ char sm[];
    const uint32_t sbase = smem_u32(sm);
    const int tid = threadIdx.x, lane = tid & 31, wid = tid >> 5;
    const bool is_comp = (wid < 8);
    const int wm = wid & 1, wn = (wid >> 1) & 3;
    const int ptid = tid & 63;

    const float* w2e = w2 + (size_t)e * HID_ * DIM_;

    const int mi = lane >> 3, lr = lane & 7;
    const uint32_t aLB = (uint32_t)((wm * 64 + (mi & 1) * 8 + lr) * ROWB + (mi >> 1) * 16);
    const uint32_t bLB = (uint32_t)((wn * 32 + (mi >> 1) * 8 + lr) * ROWB + (mi & 1) * 16);

    float acc[4][4][4];
    #pragma unroll
    for (int a = 0; a < 4; a++)
        #pragma unroll
        for (int b = 0; b < 4; b++)
            #pragma unroll
            for (int c = 0; c < 4; c++) acc[a][b][c] = 0.f;

    const int NCH = HID_ / 32;   // 176
    if (!is_comp) {
        fill_stage_ffn2(sm, sbase, ptid, e, cnt, m0, n0, 0, w2e, base);
        CP_WAIT0();
    }
    __syncthreads();

    for (int i = 0; i < NCH; i++) {
        const int s = i & 1;
        const uint32_t stS = sbase + s * STAGE_B;
        if (is_comp) {
            #pragma unroll
            for (int ks = 0; ks < 2; ks++) {
                uint32_t bh[2][4], bl[2][4];
                #pragma unroll
                for (int ng = 0; ng < 2; ng++) {
                    LDM_X4(bh[ng], stS + OFF_BH + bLB + ng * (16 * ROWB) + ks * 32);
                    LDM_X4(bl[ng], stS + OFF_BL + bLB + ng * (16 * ROWB) + ks * 32);
                }
                #pragma unroll
                for (int mt = 0; mt < 4; mt++) {
                    uint32_t ah[4], al[4];
                    LDM_X4(ah, stS + OFF_AH + aLB + mt * (16 * ROWB) + ks * 32);
                    LDM_X4(al, stS + OFF_AL + aLB + mt * (16 * ROWB) + ks * 32);
                    #pragma unroll
                    for (int ng = 0; ng < 2; ng++)
                        #pragma unroll
                        for (int h2 = 0; h2 < 2; h2++) {
                            int nt = ng * 2 + h2;
                            MMA_BF16(acc[mt][nt], ah, bh[ng][2*h2], bh[ng][2*h2+1]);
                            MMA_BF16(acc[mt][nt], al, bh[ng][2*h2], bh[ng][2*h2+1]);
                            MMA_BF16(acc[mt][nt], ah, bl[ng][2*h2], bl[ng][2*h2+1]);
                        }
                }
            }
        } else {
            if (i + 1 < NCH) {
                fill_stage_ffn2(sm + (1 - s) * STAGE_B, sbase + (1 - s) * STAGE_B,
                                ptid, e, cnt, m0, n0, (i + 1) * 32, w2e, base);
                CP_WAIT0();
            }
        }
        __syncthreads();
    }

    if (is_comp) {
        #pragma unroll
        for (int mt = 0; mt < 4; mt++)
            #pragma unroll
            for (int nt = 0; nt < 4; nt++) {
                int c = wn * 32 + nt * 8 + (lane & 3) * 2;
                #pragma unroll
                for (int rr = 0; rr < 2; rr++) {
                    int r  = wm * 64 + mt * 16 + (lane >> 2) + rr * 8;
                    int gm = m0 + r;
                    if (gm < cnt) {
                        size_t dst = (size_t)(base + gm) * DIM_ + n0 + c;
                        *(float2*)(g_y + dst) = make_float2(acc[mt][nt][2*rr], acc[mt][nt][2*rr+1]);
                    }
                }
            }
    }
}

// ---------------------------------------------------------------------------
// Combine
// ---------------------------------------------------------------------------
__global__ void combine_kernel(float* __restrict__ out) {
    const int t  = blockIdx.x;
    const int e0 = g_eid[t][0];
    const int e1 = g_eid[t][1];
    const int n0 = g_off[e0] + g_pos[t][0];
    const int n1 = g_off[e1] + g_pos[t][1];
    const float w0 = g_ew[t][0];
    const float w1 = g_ew[t][1];
    const float* y0 = &g_y[(size_t)n0 * DIM_];
    const float* y1 = &g_y[(size_t)n1 * DIM_];
    float* op = out + (size_t)t * DIM_;
    for (int d = threadIdx.x * 4; d < DIM_; d += blockDim.x * 4) {
        float4 a = *(const float4*)(y0 + d);
        float4 b = *(const float4*)(y1 + d);
        *(float4*)(op + d) = make_float4(w0 * a.x + w1 * b.x, w0 * a.y + w1 * b.y,
                                         w0 * a.z + w1 * b.z, w0 * a.w + w1 * b.w);
    }
}

// ---------------------------------------------------------------------------
// Entry point
// ---------------------------------------------------------------------------
extern "C" void kernel_launch(void* const* d_in, const int* in_sizes, int n_in,
                              void* d_out, int out_size) {
    const float* x  = (const float*)d_in[0];
    const float* gw = (const float*)d_in[1];
    const float* w1 = (const float*)d_in[2];
    const float* w2 = (const float*)d_in[3];
    const float* w3 = (const float*)d_in[4];
    float* out = (float*)d_out;

    cudaFuncSetAttribute(ffn1_kernel, cudaFuncAttributeMaxDynamicSharedMemorySize, SMEM_TOT);
    cudaFuncSetAttribute(ffn2_kernel, cudaFuncAttributeMaxDynamicSharedMemorySize, SMEM_TOT);

    gate_kernel<<<T_TOKENS, 256>>>(x, gw);
    route_kernel<<<1, 256>>>();
    split_x_kernel<<<(T_TOKENS * DIM_ / 4) / 256, 256>>>(x);
    ffn1_kernel<<<dim3(T_TOKENS / 128, HID_ / 64, NEXP), NTHREADS, SMEM_TOT>>>(w1, w3);
    ffn2_kernel<<<dim3(T_TOKENS / 128, DIM_ / 128, NEXP), NTHREADS, SMEM_TOT>>>(w2);
    combine_kernel<<<T_TOKENS, 256>>>(out);
}

// round 15
// speedup vs baseline: 3.8898x; 3.8898x over previous
#include <cuda_runtime.h>
#include <cuda_fp16.h>
#include <cuda_bf16.h>
#include <cstdint>

#define T_TOKENS 2048
#define DIM_     2048
#define HID_     5632
#define NEXP     8
#define NENT     (T_TOKENS * 2)

// ---------------------------------------------------------------------------
// Scratch (device globals — no cudaMalloc allowed)
// ---------------------------------------------------------------------------
__device__ int   g_eid [T_TOKENS][2];
__device__ float g_ew  [T_TOKENS][2];
__device__ int   g_pos [T_TOKENS][2];
__device__ int   g_list[NEXP][T_TOKENS];
__device__ int   g_cnt [NEXP];
__device__ int   g_off [NEXP];
__device__ __half g_xhi[(size_t)T_TOKENS * DIM_];   // fp16 hi of x
__device__ __half g_xlo[(size_t)T_TOKENS * DIM_];   // fp16 lo of x
__device__ __half g_hh [(size_t)NENT * HID_];       // fp16 hi of h
__device__ __half g_hl [(size_t)NENT * HID_];       // fp16 lo of h
__device__ float  g_y  [(size_t)NENT * DIM_];

// ---------------------------------------------------------------------------
// Helpers
// ---------------------------------------------------------------------------
__device__ __forceinline__ uint32_t smem_u32(const void* p) {
    uint32_t a;
    asm("{ .reg .u64 t; cvta.to.shared.u64 t, %1; cvt.u32.u64 %0, t; }" : "=r"(a) : "l"(p));
    return a;
}
__device__ __forceinline__ uint32_t pkh(__half a, __half b) {
    return (uint32_t)__half_as_ushort(a) | ((uint32_t)__half_as_ushort(b) << 16);
}
// split fp32 pair into fp16 hi pair + fp16 lo pair
__device__ __forceinline__ void split_pair_h(float f0, float f1, uint32_t& hp, uint32_t& lp) {
    __half h0 = __float2half_rn(f0);
    __half h1 = __float2half_rn(f1);
    __half l0 = __float2half_rn(f0 - __half2float(h0));
    __half l1 = __float2half_rn(f1 - __half2float(h1));
    hp = pkh(h0, h1);
    lp = pkh(l0, l1);
}
// single fp16 pair
__device__ __forceinline__ uint32_t pack_h(float f0, float f1) {
    return pkh(__float2half_rn(f0), __float2half_rn(f1));
}

#define LDM_X4(r, addr)                                                          \
    asm volatile("ldmatrix.sync.aligned.m8n8.x4.shared.b16 {%0,%1,%2,%3}, [%4];" \
        : "=r"((r)[0]), "=r"((r)[1]), "=r"((r)[2]), "=r"((r)[3]) : "r"(addr))

#define MMA_F16(d, a, b0, b1)                                                    \
    asm volatile("mma.sync.aligned.m16n8k16.row.col.f32.f16.f16.f32 "            \
        "{%0,%1,%2,%3}, {%4,%5,%6,%7}, {%8,%9}, {%0,%1,%2,%3};"                  \
        : "+f"((d)[0]), "+f"((d)[1]), "+f"((d)[2]), "+f"((d)[3])                 \
        : "r"((a)[0]), "r"((a)[1]), "r"((a)[2]), "r"((a)[3]), "r"(b0), "r"(b1))

#define CP_ASYNC16(dst, src)                                                     \
    asm volatile("cp.async.cg.shared.global [%0], [%1], 16;" :: "r"(dst), "l"(src))
#define CP_COMMIT() asm volatile("cp.async.commit_group;" ::: "memory")
#define CP_WAIT0()  asm volatile("cp.async.wait_group 0;" ::: "memory")

// Smem: rows of 32 fp16 padded to 80B -> conflict-free ldmatrix (proven R4-R13)
#define ROWB     80
#define TILE_A   10240          // 128 rows * 80B (one A matrix: hi or lo)
#define OFF_AH   0
#define OFF_AL   10240
#define OFF_B    20480          // B: single fp16 matrix, 128 rows * 80B
#define STAGE_B  30720
#define SMEM_TOT (2 * STAGE_B)  // 61440; 2 CTAs/SM (regs-capped at 128)

// ---------------------------------------------------------------------------
// Gating + routing + x split (gate stays full fp32 — expert choice must be exact)
// ---------------------------------------------------------------------------
__global__ void gate_kernel(const float* __restrict__ x, const float* __restrict__ gw) {
    const int t = blockIdx.x, lane = threadIdx.x & 31, w = threadIdx.x >> 5;
    const float* xr = x + (size_t)t * DIM_;
    const float* gr = gw + (size_t)w * DIM_;
    float s = 0.f;
    for (int d = lane * 4; d < DIM_; d += 128) {
        float4 a = *(const float4*)(xr + d);
        float4 b = *(const float4*)(gr + d);
        s += a.x * b.x + a.y * b.y + a.z * b.z + a.w * b.w;
    }
    #pragma unroll
    for (int o = 16; o; o >>= 1) s += __shfl_xor_sync(0xffffffffu, s, o);
    __shared__ float sc[NEXP];
    if (lane == 0) sc[w] = s;
    __syncthreads();
    if (threadIdx.x == 0) {
        int b0 = 0; float s0 = sc[0];
        #pragma unroll
        for (int e = 1; e < NEXP; e++) if (sc[e] > s0) { s0 = sc[e]; b0 = e; }
        int b1 = -1; float s1 = -1e30f;
        #pragma unroll
        for (int e = 0; e < NEXP; e++) if (e != b0 && sc[e] > s1) { s1 = sc[e]; b1 = e; }
        float e1 = __expf(s1 - s0);
        float inv = 1.f / (1.f + e1);
        g_eid[t][0] = b0; g_eid[t][1] = b1;
        g_ew [t][0] = inv; g_ew [t][1] = e1 * inv;
    }
}

__global__ void route_kernel() {
    const int lane = threadIdx.x & 31, e = threadIdx.x >> 5;
    if (e < NEXP) {
        int cnt = 0;
        for (int t0 = 0; t0 < T_TOKENS; t0 += 32) {
            int t = t0 + lane;
            int e0 = g_eid[t][0], e1 = g_eid[t][1];
            bool sel = (e0 == e) || (e1 == e);
            int slot = (e0 == e) ? 0 : 1;
            unsigned m = __ballot_sync(0xffffffffu, sel);
            if (sel) {
                int p = cnt + __popc(m & ((1u << lane) - 1u));
                g_list[e][p] = t;
                g_pos[t][slot] = p;
            }
            cnt += __popc(m);
        }
        if (lane == 0) g_cnt[e] = cnt;
    }
    __syncthreads();
    if (threadIdx.x == 0) {
        int off = 0;
        #pragma unroll
        for (int i = 0; i < NEXP; i++) { g_off[i] = off; off += g_cnt[i]; }
    }
}

__global__ void split_x_kernel(const float* __restrict__ x) {
    int i = blockIdx.x * blockDim.x + threadIdx.x;
    float4 v = ((const float4*)x)[i];
    size_t o = (size_t)i * 4;
    float vv[4] = {v.x, v.y, v.z, v.w};
    #pragma unroll
    for (int k = 0; k < 4; k++) {
        __half h = __float2half_rn(vv[k]);
        g_xhi[o + k] = h;
        g_xlo[o + k] = __float2half_rn(vv[k] - __half2float(h));
    }
}

// ---------------------------------------------------------------------------
// GEMM1: u = x@w1, v = x@w3.  A = fp16 hi+lo split of x; B = single fp16
// (w1/w3 interleaved rows: row 2j = w1 col j, 2j+1 = w3 col j so (u,v) land
// in one thread's (d0,d1)).  2 MMAs per acc.  256 threads (2m x 4n warps,
// warp tile 64x32), CTA 128 tokens x 64 h-cols, BK=32, 2-stage, 1 barrier/iter.
// ---------------------------------------------------------------------------
__global__ void __launch_bounds__(256, 2) ffn1_kernel(const float* __restrict__ w1,
                                                      const float* __restrict__ w3) {
    const int e   = blockIdx.z;
    const int cnt = g_cnt[e];
    const int m0  = blockIdx.x * 128;
    if (m0 >= cnt) return;
    const int n0   = blockIdx.y * 64;     // h-cols
    const int base = g_off[e];

    extern __shared__ char sm[];
    const uint32_t sbase = smem_u32(sm);
    const int tid = threadIdx.x, lane = tid & 31, wid = tid >> 5;
    const int wm = wid & 1, wn = wid >> 1;

    const float* w1e = w1 + (size_t)e * DIM_ * HID_;
    const float* w3e = w3 + (size_t)e * DIM_ * HID_;

    // A loader: 1024 cp.async chunks (2 mats x 128 rows x 4 kq), 4/thread
    const __half* apA[4];
    uint32_t aoA[4];
    #pragma unroll
    for (int q = 0; q < 4; q++) {
        int idx = tid + q * 256;
        int mat = idx >> 9;
        int rem = idx & 511;
        int row = rem >> 2, kq = rem & 3;
        int tok = g_list[e][min(m0 + row, cnt - 1)];
        apA[q] = (mat ? g_xlo : g_xhi) + (size_t)tok * DIM_ + kq * 8;
        aoA[q] = mat * TILE_A + row * ROWB + kq * 16;
    }
    // B loader: 512 tasks (128 interleaved rows x 4 k-blocks), 2/thread
    int bnT[2], bkT[2];
    const float* pB[2];
    #pragma unroll
    for (int r = 0; r < 2; r++) {
        int task = tid + r * 256;
        bnT[r] = task & 127;
        bkT[r] = task >> 7;
        pB[r]  = ((bnT[r] & 1) ? w3e : w1e) + (size_t)(bkT[r] * 8) * HID_ + (n0 + (bnT[r] >> 1));
    }

    const int mi = lane >> 3, lr = lane & 7;
    const uint32_t aLB = (uint32_t)((wm * 64 + (mi & 1) * 8 + lr) * ROWB + (mi >> 1) * 16);
    const uint32_t bLB = (uint32_t)((wn * 32 + (mi >> 1) * 8 + lr) * ROWB + (mi & 1) * 16);

    float acc[4][4][4];
    #pragma unroll
    for (int a = 0; a < 4; a++)
        #pragma unroll
        for (int b = 0; b < 4; b++)
            #pragma unroll
            for (int c = 0; c < 4; c++) acc[a][b][c] = 0.f;

    // ---- prologue: stage 0 ----
    #pragma unroll
    for (int q = 0; q < 4; q++) CP_ASYNC16(sbase + aoA[q], apA[q]);
    CP_COMMIT();
    #pragma unroll
    for (int r = 0; r < 2; r++) {
        float f[8];
        #pragma unroll
        for (int j = 0; j < 8; j++) f[j] = pB[r][(size_t)j * HID_];
        uint32_t bo = bnT[r] * ROWB + bkT[r] * 16;
        *(uint4*)(sm + OFF_B + bo) = make_uint4(pack_h(f[0], f[1]), pack_h(f[2], f[3]),
                                                pack_h(f[4], f[5]), pack_h(f[6], f[7]));
    }
    CP_WAIT0();
    __syncthreads();

    const int NCH = DIM_ / 32;   // 64
    for (int i = 0; i < NCH; i++) {
        const int s = i & 1;
        const uint32_t stS = sbase + s * STAGE_B;
        // fill stage i+1 while computing stage i
        if (i + 1 < NCH) {
            const uint32_t stN = sbase + (1 - s) * STAGE_B;
            char* stNc = sm + (1 - s) * STAGE_B;
            int kk = (i + 1) * 32;
            #pragma unroll
            for (int q = 0; q < 4; q++) CP_ASYNC16(stN + aoA[q], apA[q] + kk);
            CP_COMMIT();
            #pragma unroll
            for (int r = 0; r < 2; r++) {
                float f[8];
                #pragma unroll
                for (int j = 0; j < 8; j++) f[j] = pB[r][(size_t)(kk + j) * HID_];
                uint32_t bo = bnT[r] * ROWB + bkT[r] * 16;
                *(uint4*)(stNc + OFF_B + bo) = make_uint4(pack_h(f[0], f[1]), pack_h(f[2], f[3]),
                                                          pack_h(f[4], f[5]), pack_h(f[6], f[7]));
            }
        }
        // compute stage i (2 MMAs per acc: ah*b + al*b)
        #pragma unroll
        for (int ks = 0; ks < 2; ks++) {
            uint32_t bh[2][4];
            #pragma unroll
            for (int ng = 0; ng < 2; ng++)
                LDM_X4(bh[ng], stS + OFF_B + bLB + ng * (16 * ROWB) + ks * 32);
            #pragma unroll
            for (int mt = 0; mt < 4; mt++) {
                uint32_t ah[4], al[4];
                LDM_X4(ah, stS + OFF_AH + aLB + mt * (16 * ROWB) + ks * 32);
                LDM_X4(al, stS + OFF_AL + aLB + mt * (16 * ROWB) + ks * 32);
                #pragma unroll
                for (int ng = 0; ng < 2; ng++)
                    #pragma unroll
                    for (int h2 = 0; h2 < 2; h2++) {
                        int nt = ng * 2 + h2;
                        MMA_F16(acc[mt][nt], ah, bh[ng][2*h2], bh[ng][2*h2+1]);
                        MMA_F16(acc[mt][nt], al, bh[ng][2*h2], bh[ng][2*h2+1]);
                    }
            }
        }
        CP_WAIT0();
        __syncthreads();
    }

    // epilogue: d0=u, d1=v for the same h-col, in-register SwiGLU, fp16 split
    #pragma unroll
    for (int mt = 0; mt < 4; mt++)
        #pragma unroll
        for (int nt = 0; nt < 4; nt++) {
            int j = wn * 16 + nt * 4 + (lane & 3);
            #pragma unroll
            for (int rr = 0; rr < 2; rr++) {
                int r  = wm * 64 + mt * 16 + (lane >> 2) + rr * 8;
                int gm = m0 + r;
                float u = acc[mt][nt][2*rr], v = acc[mt][nt][2*rr+1];
                float h = u / (1.f + __expf(-u)) * v;
                __half hh = __float2half_rn(h);
                __half hl = __float2half_rn(h - __half2float(hh));
                if (gm < cnt) {
                    size_t dst = (size_t)(base + gm) * HID_ + n0 + j;
                    g_hh[dst] = hh;
                    g_hl[dst] = hl;
                }
            }
        }
}

// ---------------------------------------------------------------------------
// GEMM2: y = h @ w2.  A = fp16 hi+lo split of h; B = single fp16 w2.
// 256 threads, warp tile 64x32, CTA 128 x 128.
// ---------------------------------------------------------------------------
__global__ void __launch_bounds__(256, 2) ffn2_kernel(const float* __restrict__ w2) {
    const int e   = blockIdx.z;
    const int cnt = g_cnt[e];
    const int m0  = blockIdx.x * 128;
    if (m0 >= cnt) return;
    const int n0   = blockIdx.y * 128;
    const int base = g_off[e];

    extern __shared__ char sm[];
    const uint32_t sbase = smem_u32(sm);
    const int tid = threadIdx.x, lane = tid & 31, wid = tid >> 5;
    const int wm = wid & 1, wn = wid >> 1;

    const float* w2e = w2 + (size_t)e * HID_ * DIM_;

    const __half* apA[4];
    uint32_t aoA[4];
    #pragma unroll
    for (int q = 0; q < 4; q++) {
        int idx = tid + q * 256;
        int mat = idx >> 9;
        int rem = idx & 511;
        int row = rem >> 2, kq = rem & 3;
        int r   = base + min(m0 + row, cnt - 1);
        apA[q] = (mat ? g_hl : g_hh) + (size_t)r * HID_ + kq * 8;
        aoA[q] = mat * TILE_A + row * ROWB + kq * 16;
    }
    int bnT[2], bkT[2];
    const float* pB[2];
    #pragma unroll
    for (int r = 0; r < 2; r++) {
        int task = tid + r * 256;
        bnT[r] = task & 127;
        bkT[r] = task >> 7;
        pB[r]  = w2e + (size_t)(bkT[r] * 8) * DIM_ + (n0 + bnT[r]);
    }

    const int mi = lane >> 3, lr = lane & 7;
    const uint32_t aLB = (uint32_t)((wm * 64 + (mi & 1) * 8 + lr) * ROWB + (mi >> 1) * 16);
    const uint32_t bLB = (uint32_t)((wn * 32 + (mi >> 1) * 8 + lr) * ROWB + (mi & 1) * 16);

    float acc[4][4][4];
    #pragma unroll
    for (int a = 0; a < 4; a++)
        #pragma unroll
        for (int b = 0; b < 4; b++)
            #pragma unroll
            for (int c = 0; c < 4; c++) acc[a][b][c] = 0.f;

    #pragma unroll
    for (int q = 0; q < 4; q++) CP_ASYNC16(sbase + aoA[q], apA[q]);
    CP_COMMIT();
    #pragma unroll
    for (int r = 0; r < 2; r++) {
        float f[8];
        #pragma unroll
        for (int j = 0; j < 8; j++) f[j] = pB[r][(size_t)j * DIM_];
        uint32_t bo = bnT[r] * ROWB + bkT[r] * 16;
        *(uint4*)(sm + OFF_B + bo) = make_uint4(pack_h(f[0], f[1]), pack_h(f[2], f[3]),
                                                pack_h(f[4], f[5]), pack_h(f[6], f[7]));
    }
    CP_WAIT0();
    __syncthreads();

    const int NCH = HID_ / 32;   // 176
    for (int i = 0; i < NCH; i++) {
        const int s = i & 1;
        const uint32_t stS = sbase + s * STAGE_B;
        if (i + 1 < NCH) {
            const uint32_t stN = sbase + (1 - s) * STAGE_B;
            char* stNc = sm + (1 - s) * STAGE_B;
            int kk = (i + 1) * 32;
            #pragma unroll
            for (int q = 0; q < 4; q++) CP_ASYNC16(stN + aoA[q], apA[q] + kk);
            CP_COMMIT();
            #pragma unroll
            for (int r = 0; r < 2; r++) {
                float f[8];
                #pragma unroll
                for (int j = 0; j < 8; j++) f[j] = pB[r][(size_t)(kk + j) * DIM_];
                uint32_t bo = bnT[r] * ROWB + bkT[r] * 16;
                *(uint4*)(stNc + OFF_B + bo) = make_uint4(pack_h(f[0], f[1]), pack_h(f[2], f[3]),
                                                          pack_h(f[4], f[5]), pack_h(f[6], f[7]));
            }
        }
        #pragma unroll
        for (int ks = 0; ks < 2; ks++) {
            uint32_t bh[2][4];
            #pragma unroll
            for (int ng = 0; ng < 2; ng++)
                LDM_X4(bh[ng], stS + OFF_B + bLB + ng * (16 * ROWB) + ks * 32);
            #pragma unroll
            for (int mt = 0; mt < 4; mt++) {
                uint32_t ah[4], al[4];
                LDM_X4(ah, stS + OFF_AH + aLB + mt * (16 * ROWB) + ks * 32);
                LDM_X4(al, stS + OFF_AL + aLB + mt * (16 * ROWB) + ks * 32);
                #pragma unroll
                for (int ng = 0; ng < 2; ng++)
                    #pragma unroll
                    for (int h2 = 0; h2 < 2; h2++) {
                        int nt = ng * 2 + h2;
                        MMA_F16(acc[mt][nt], ah, bh[ng][2*h2], bh[ng][2*h2+1]);
                        MMA_F16(acc[mt][nt], al, bh[ng][2*h2], bh[ng][2*h2+1]);
                    }
            }
        }
        CP_WAIT0();
        __syncthreads();
    }

    #pragma unroll
    for (int mt = 0; mt < 4; mt++)
        #pragma unroll
        for (int nt = 0; nt < 4; nt++) {
            int c = wn * 32 + nt * 8 + (lane & 3) * 2;
            #pragma unroll
            for (int rr = 0; rr < 2; rr++) {
                int r  = wm * 64 + mt * 16 + (lane >> 2) + rr * 8;
                int gm = m0 + r;
                if (gm < cnt) {
                    size_t dst = (size_t)(base + gm) * DIM_ + n0 + c;
                    *(float2*)(g_y + dst) = make_float2(acc[mt][nt][2*rr], acc[mt][nt][2*rr+1]);
                }
            }
        }
}

// ---------------------------------------------------------------------------
// Combine
// ---------------------------------------------------------------------------
__global__ void combine_kernel(float* __restrict__ out) {
    const int t  = blockIdx.x;
    const int e0 = g_eid[t][0];
    const int e1 = g_eid[t][1];
    const int n0 = g_off[e0] + g_pos[t][0];
    const int n1 = g_off[e1] + g_pos[t][1];
    const float w0 = g_ew[t][0];
    const float w1 = g_ew[t][1];
    const float* y0 = &g_y[(size_t)n0 * DIM_];
    const float* y1 = &g_y[(size_t)n1 * DIM_];
    float* op = out + (size_t)t * DIM_;
    for (int d = threadIdx.x * 4; d < DIM_; d += blockDim.x * 4) {
        float4 a = *(const float4*)(y0 + d);
        float4 b = *(const float4*)(y1 + d);
        *(float4*)(op + d) = make_float4(w0 * a.x + w1 * b.x, w0 * a.y + w1 * b.y,
                                         w0 * a.z + w1 * b.z, w0 * a.w + w1 * b.w);
    }
}

// ---------------------------------------------------------------------------
// Entry point
// ---------------------------------------------------------------------------
extern "C" void kernel_launch(void* const* d_in, const int* in_sizes, int n_in,
                              void* d_out, int out_size) {
    const float* x  = (const float*)d_in[0];
    const float* gw = (const float*)d_in[1];
    const float* w1 = (const float*)d_in[2];
    const float* w2 = (const float*)d_in[3];
    const float* w3 = (const float*)d_in[4];
    float* out = (float*)d_out;

    cudaFuncSetAttribute(ffn1_kernel, cudaFuncAttributeMaxDynamicSharedMemorySize, SMEM_TOT);
    cudaFuncSetAttribute(ffn2_kernel, cudaFuncAttributeMaxDynamicSharedMemorySize, SMEM_TOT);

    gate_kernel<<<T_TOKENS, 256>>>(x, gw);
    route_kernel<<<1, 256>>>();
    split_x_kernel<<<(T_TOKENS * DIM_ / 4) / 256, 256>>>(x);
    ffn1_kernel<<<dim3(T_TOKENS / 128, HID_ / 64, NEXP), 256, SMEM_TOT>>>(w1, w3);
    ffn2_kernel<<<dim3(T_TOKENS / 128, DIM_ / 128, NEXP), 256, SMEM_TOT>>>(w2);
    combine_kernel<<<T_TOKENS, 256>>>(out);
}

// round 16
// speedup vs baseline: 4.9967x; 1.2845x over previous
#include <cuda_runtime.h>
#include <cuda_fp16.h>
#include <cstdint>

#define T_TOKENS 2048
#define DIM_     2048
#define HID_     5632
#define NEXP     8
#define NENT     (T_TOKENS * 2)

// ---------------------------------------------------------------------------
// Scratch (device globals — no cudaMalloc allowed)
// ---------------------------------------------------------------------------
__device__ int   g_eid [T_TOKENS][2];
__device__ float g_ew  [T_TOKENS][2];
__device__ int   g_pos [T_TOKENS][2];
__device__ int   g_list[NEXP][T_TOKENS];
__device__ int   g_cnt [NEXP];
__device__ int   g_off [NEXP];
__device__ __half g_xh[(size_t)T_TOKENS * DIM_];   // fp16 x
__device__ __half g_hh[(size_t)NENT * HID_];       // fp16 h
__device__ float  g_y [(size_t)NENT * DIM_];

// ---------------------------------------------------------------------------
// Helpers
// ---------------------------------------------------------------------------
__device__ __forceinline__ uint32_t smem_u32(const void* p) {
    uint32_t a;
    asm("{ .reg .u64 t; cvta.to.shared.u64 t, %1; cvt.u32.u64 %0, t; }" : "=r"(a) : "l"(p));
    return a;
}
__device__ __forceinline__ uint32_t pack_h(float f0, float f1) {
    return (uint32_t)__half_as_ushort(__float2half_rn(f0))
         | ((uint32_t)__half_as_ushort(__float2half_rn(f1)) << 16);
}

#define LDM_X4(r, addr)                                                          \
    asm volatile("ldmatrix.sync.aligned.m8n8.x4.shared.b16 {%0,%1,%2,%3}, [%4];" \
        : "=r"((r)[0]), "=r"((r)[1]), "=r"((r)[2]), "=r"((r)[3]) : "r"(addr))

#define MMA_F16(d, a, b0, b1)                                                    \
    asm volatile("mma.sync.aligned.m16n8k16.row.col.f32.f16.f16.f32 "            \
        "{%0,%1,%2,%3}, {%4,%5,%6,%7}, {%8,%9}, {%0,%1,%2,%3};"                  \
        : "+f"((d)[0]), "+f"((d)[1]), "+f"((d)[2]), "+f"((d)[3])                 \
        : "r"((a)[0]), "r"((a)[1]), "r"((a)[2]), "r"((a)[3]), "r"(b0), "r"(b1))

#define CP_ASYNC16(dst, src)                                                     \
    asm volatile("cp.async.cg.shared.global [%0], [%1], 16;" :: "r"(dst), "l"(src))
#define CP_COMMIT() asm volatile("cp.async.commit_group;" ::: "memory")
#define CP_WAIT0()  asm volatile("cp.async.wait_group 0;" ::: "memory")

// Smem: rows of 32 fp16 padded to 80B -> conflict-free ldmatrix (proven R4-R15)
#define ROWB     80
#define TILE_A   10240          // 128 rows * 80B
#define OFF_A    0
#define OFF_B    10240          // B: single fp16 matrix, 128 rows * 80B
#define STAGE_B  20480
#define SMEM_TOT (2 * STAGE_B)  // 40960; 2 CTAs/SM (regs cap)

// ---------------------------------------------------------------------------
// Gating + routing + x convert (gate stays full fp32 — routing must be exact)
// ---------------------------------------------------------------------------
__global__ void gate_kernel(const float* __restrict__ x, const float* __restrict__ gw) {
    const int t = blockIdx.x, lane = threadIdx.x & 31, w = threadIdx.x >> 5;
    const float* xr = x + (size_t)t * DIM_;
    const float* gr = gw + (size_t)w * DIM_;
    float s = 0.f;
    for (int d = lane * 4; d < DIM_; d += 128) {
        float4 a = *(const float4*)(xr + d);
        float4 b = *(const float4*)(gr + d);
        s += a.x * b.x + a.y * b.y + a.z * b.z + a.w * b.w;
    }
    #pragma unroll
    for (int o = 16; o; o >>= 1) s += __shfl_xor_sync(0xffffffffu, s, o);
    __shared__ float sc[NEXP];
    if (lane == 0) sc[w] = s;
    __syncthreads();
    if (threadIdx.x == 0) {
        int b0 = 0; float s0 = sc[0];
        #pragma unroll
        for (int e = 1; e < NEXP; e++) if (sc[e] > s0) { s0 = sc[e]; b0 = e; }
        int b1 = -1; float s1 = -1e30f;
        #pragma unroll
        for (int e = 0; e < NEXP; e++) if (e != b0 && sc[e] > s1) { s1 = sc[e]; b1 = e; }
        float e1 = __expf(s1 - s0);
        float inv = 1.f / (1.f + e1);
        g_eid[t][0] = b0; g_eid[t][1] = b1;
        g_ew [t][0] = inv; g_ew [t][1] = e1 * inv;
    }
}

__global__ void route_kernel() {
    const int lane = threadIdx.x & 31, e = threadIdx.x >> 5;
    if (e < NEXP) {
        int cnt = 0;
        for (int t0 = 0; t0 < T_TOKENS; t0 += 32) {
            int t = t0 + lane;
            int e0 = g_eid[t][0], e1 = g_eid[t][1];
            bool sel = (e0 == e) || (e1 == e);
            int slot = (e0 == e) ? 0 : 1;
            unsigned m = __ballot_sync(0xffffffffu, sel);
            if (sel) {
                int p = cnt + __popc(m & ((1u << lane) - 1u));
                g_list[e][p] = t;
                g_pos[t][slot] = p;
            }
            cnt += __popc(m);
        }
        if (lane == 0) g_cnt[e] = cnt;
    }
    __syncthreads();
    if (threadIdx.x == 0) {
        int off = 0;
        #pragma unroll
        for (int i = 0; i < NEXP; i++) { g_off[i] = off; off += g_cnt[i]; }
    }
}

__global__ void cvt_x_kernel(const float* __restrict__ x) {
    int i = blockIdx.x * blockDim.x + threadIdx.x;
    float4 v = ((const float4*)x)[i];
    size_t o = (size_t)i * 4;
    g_xh[o + 0] = __float2half_rn(v.x);
    g_xh[o + 1] = __float2half_rn(v.y);
    g_xh[o + 2] = __float2half_rn(v.z);
    g_xh[o + 3] = __float2half_rn(v.w);
}

// ---------------------------------------------------------------------------
// GEMM1: u = x@w1, v = x@w3.  A = fp16 x; B = fp16 (w1/w3 interleaved rows:
// row 2j = w1 col j, 2j+1 = w3 col j so (u,v) land in one thread's (d0,d1)).
// 1 MMA per acc.  256 threads (2m x 4n warps, warp tile 64x32),
// CTA 128 tokens x 64 h-cols, BK=32, 2-stage, 1 barrier/iter.
// ---------------------------------------------------------------------------
__global__ void __launch_bounds__(256, 2) ffn1_kernel(const float* __restrict__ w1,
                                                      const float* __restrict__ w3) {
    const int e   = blockIdx.z;
    const int cnt = g_cnt[e];
    const int m0  = blockIdx.x * 128;
    if (m0 >= cnt) return;
    const int n0   = blockIdx.y * 64;     // h-cols
    const int base = g_off[e];

    extern __shared__ char sm[];
    const uint32_t sbase = smem_u32(sm);
    const int tid = threadIdx.x, lane = tid & 31, wid = tid >> 5;
    const int wm = wid & 1, wn = wid >> 1;

    const float* w1e = w1 + (size_t)e * DIM_ * HID_;
    const float* w3e = w3 + (size_t)e * DIM_ * HID_;

    // A loader: 512 cp.async chunks (128 rows x 4 kq), 2/thread
    const __half* apA[2];
    uint32_t aoA[2];
    #pragma unroll
    for (int q = 0; q < 2; q++) {
        int idx = tid + q * 256;
        int row = idx >> 2, kq = idx & 3;
        int tok = g_list[e][min(m0 + row, cnt - 1)];
        apA[q] = g_xh + (size_t)tok * DIM_ + kq * 8;
        aoA[q] = row * ROWB + kq * 16;
    }
    // B loader: 512 tasks (128 interleaved rows x 4 k-blocks), 2/thread
    int bnT[2], bkT[2];
    const float* pB[2];
    #pragma unroll
    for (int r = 0; r < 2; r++) {
        int task = tid + r * 256;
        bnT[r] = task & 127;
        bkT[r] = task >> 7;
        pB[r]  = ((bnT[r] & 1) ? w3e : w1e) + (size_t)(bkT[r] * 8) * HID_ + (n0 + (bnT[r] >> 1));
    }

    const int mi = lane >> 3, lr = lane & 7;
    const uint32_t aLB = (uint32_t)((wm * 64 + (mi & 1) * 8 + lr) * ROWB + (mi >> 1) * 16);
    const uint32_t bLB = (uint32_t)((wn * 32 + (mi >> 1) * 8 + lr) * ROWB + (mi & 1) * 16);

    float acc[4][4][4];
    #pragma unroll
    for (int a = 0; a < 4; a++)
        #pragma unroll
        for (int b = 0; b < 4; b++)
            #pragma unroll
            for (int c = 0; c < 4; c++) acc[a][b][c] = 0.f;

    // ---- prologue: stage 0 ----
    #pragma unroll
    for (int q = 0; q < 2; q++) CP_ASYNC16(sbase + OFF_A + aoA[q], apA[q]);
    CP_COMMIT();
    #pragma unroll
    for (int r = 0; r < 2; r++) {
        float f[8];
        #pragma unroll
        for (int j = 0; j < 8; j++) f[j] = pB[r][(size_t)j * HID_];
        uint32_t bo = bnT[r] * ROWB + bkT[r] * 16;
        *(uint4*)(sm + OFF_B + bo) = make_uint4(pack_h(f[0], f[1]), pack_h(f[2], f[3]),
                                                pack_h(f[4], f[5]), pack_h(f[6], f[7]));
    }
    CP_WAIT0();
    __syncthreads();

    const int NCH = DIM_ / 32;   // 64
    for (int i = 0; i < NCH; i++) {
        const int s = i & 1;
        const uint32_t stS = sbase + s * STAGE_B;
        // fill stage i+1 while computing stage i
        if (i + 1 < NCH) {
            const uint32_t stN = sbase + (1 - s) * STAGE_B;
            char* stNc = sm + (1 - s) * STAGE_B;
            int kk = (i + 1) * 32;
            #pragma unroll
            for (int q = 0; q < 2; q++) CP_ASYNC16(stN + OFF_A + aoA[q], apA[q] + kk);
            CP_COMMIT();
            #pragma unroll
            for (int r = 0; r < 2; r++) {
                float f[8];
                #pragma unroll
                for (int j = 0; j < 8; j++) f[j] = pB[r][(size_t)(kk + j) * HID_];
                uint32_t bo = bnT[r] * ROWB + bkT[r] * 16;
                *(uint4*)(stNc + OFF_B + bo) = make_uint4(pack_h(f[0], f[1]), pack_h(f[2], f[3]),
                                                          pack_h(f[4], f[5]), pack_h(f[6], f[7]));
            }
        }
        // compute stage i (1 MMA per acc)
        #pragma unroll
        for (int ks = 0; ks < 2; ks++) {
            uint32_t bh[2][4];
            #pragma unroll
            for (int ng = 0; ng < 2; ng++)
                LDM_X4(bh[ng], stS + OFF_B + bLB + ng * (16 * ROWB) + ks * 32);
            #pragma unroll
            for (int mt = 0; mt < 4; mt++) {
                uint32_t ah[4];
                LDM_X4(ah, stS + OFF_A + aLB + mt * (16 * ROWB) + ks * 32);
                #pragma unroll
                for (int ng = 0; ng < 2; ng++)
                    #pragma unroll
                    for (int h2 = 0; h2 < 2; h2++)
                        MMA_F16(acc[mt][ng*2+h2], ah, bh[ng][2*h2], bh[ng][2*h2+1]);
            }
        }
        CP_WAIT0();
        __syncthreads();
    }

    // epilogue: d0=u, d1=v for the same h-col, in-register SwiGLU
    #pragma unroll
    for (int mt = 0; mt < 4; mt++)
        #pragma unroll
        for (int nt = 0; nt < 4; nt++) {
            int j = wn * 16 + nt * 4 + (lane & 3);
            #pragma unroll
            for (int rr = 0; rr < 2; rr++) {
                int r  = wm * 64 + mt * 16 + (lane >> 2) + rr * 8;
                int gm = m0 + r;
                float u = acc[mt][nt][2*rr], v = acc[mt][nt][2*rr+1];
                float h = u / (1.f + __expf(-u)) * v;
                if (gm < cnt) {
                    size_t dst = (size_t)(base + gm) * HID_ + n0 + j;
                    g_hh[dst] = __float2half_rn(h);
                }
            }
        }
}

// ---------------------------------------------------------------------------
// GEMM2: y = h @ w2.  A = fp16 h; B = fp16 w2.  1 MMA per acc.
// 256 threads, warp tile 64x32, CTA 128 x 128.
// ---------------------------------------------------------------------------
__global__ void __launch_bounds__(256, 2) ffn2_kernel(const float* __restrict__ w2) {
    const int e   = blockIdx.z;
    const int cnt = g_cnt[e];
    const int m0  = blockIdx.x * 128;
    if (m0 >= cnt) return;
    const int n0   = blockIdx.y * 128;
    const int base = g_off[e];

    extern __shared__ char sm[];
    const uint32_t sbase = smem_u32(sm);
    const int tid = threadIdx.x, lane = tid & 31, wid = tid >> 5;
    const int wm = wid & 1, wn = wid >> 1;

    const float* w2e = w2 + (size_t)e * HID_ * DIM_;

    const __half* apA[2];
    uint32_t aoA[2];
    #pragma unroll
    for (int q = 0; q < 2; q++) {
        int idx = tid + q * 256;
        int row = idx >> 2, kq = idx & 3;
        int r   = base + min(m0 + row, cnt - 1);
        apA[q] = g_hh + (size_t)r * HID_ + kq * 8;
        aoA[q] = row * ROWB + kq * 16;
    }
    int bnT[2], bkT[2];
    const float* pB[2];
    #pragma unroll
    for (int r = 0; r < 2; r++) {
        int task = tid + r * 256;
        bnT[r] = task & 127;
        bkT[r] = task >> 7;
        pB[r]  = w2e + (size_t)(bkT[r] * 8) * DIM_ + (n0 + bnT[r]);
    }

    const int mi = lane >> 3, lr = lane & 7;
    const uint32_t aLB = (uint32_t)((wm * 64 + (mi & 1) * 8 + lr) * ROWB + (mi >> 1) * 16);
    const uint32_t bLB = (uint32_t)((wn * 32 + (mi >> 1) * 8 + lr) * ROWB + (mi & 1) * 16);

    float acc[4][4][4];
    #pragma unroll
    for (int a = 0; a < 4; a++)
        #pragma unroll
        for (int b = 0; b < 4; b++)
            #pragma unroll
            for (int c = 0; c < 4; c++) acc[a][b][c] = 0.f;

    #pragma unroll
    for (int q = 0; q < 2; q++) CP_ASYNC16(sbase + OFF_A + aoA[q], apA[q]);
    CP_COMMIT();
    #pragma unroll
    for (int r = 0; r < 2; r++) {
        float f[8];
        #pragma unroll
        for (int j = 0; j < 8; j++) f[j] = pB[r][(size_t)j * DIM_];
        uint32_t bo = bnT[r] * ROWB + bkT[r] * 16;
        *(uint4*)(sm + OFF_B + bo) = make_uint4(pack_h(f[0], f[1]), pack_h(f[2], f[3]),
                                                pack_h(f[4], f[5]), pack_h(f[6], f[7]));
    }
    CP_WAIT0();
    __syncthreads();

    const int NCH = HID_ / 32;   // 176
    for (int i = 0; i < NCH; i++) {
        const int s = i & 1;
        const uint32_t stS = sbase + s * STAGE_B;
        if (i + 1 < NCH) {
            const uint32_t stN = sbase + (1 - s) * STAGE_B;
            char* stNc = sm + (1 - s) * STAGE_B;
            int kk = (i + 1) * 32;
            #pragma unroll
            for (int q = 0; q < 2; q++) CP_ASYNC16(stN + OFF_A + aoA[q], apA[q] + kk);
            CP_COMMIT();
            #pragma unroll
            for (int r = 0; r < 2; r++) {
                float f[8];
                #pragma unroll
                for (int j = 0; j < 8; j++) f[j] = pB[r][(size_t)(kk + j) * DIM_];
                uint32_t bo = bnT[r] * ROWB + bkT[r] * 16;
                *(uint4*)(stNc + OFF_B + bo) = make_uint4(pack_h(f[0], f[1]), pack_h(f[2], f[3]),
                                                          pack_h(f[4], f[5]), pack_h(f[6], f[7]));
            }
        }
        #pragma unroll
        for (int ks = 0; ks < 2; ks++) {
            uint32_t bh[2][4];
            #pragma unroll
            for (int ng = 0; ng < 2; ng++)
                LDM_X4(bh[ng], stS + OFF_B + bLB + ng * (16 * ROWB) + ks * 32);
            #pragma unroll
            for (int mt = 0; mt < 4; mt++) {
                uint32_t ah[4];
                LDM_X4(ah, stS + OFF_A + aLB + mt * (16 * ROWB) + ks * 32);
                #pragma unroll
                for (int ng = 0; ng < 2; ng++)
                    #pragma unroll
                    for (int h2 = 0; h2 < 2; h2++)
                        MMA_F16(acc[mt][ng*2+h2], ah, bh[ng][2*h2], bh[ng][2*h2+1]);
            }
        }
        CP_WAIT0();
        __syncthreads();
    }

    #pragma unroll
    for (int mt = 0; mt < 4; mt++)
        #pragma unroll
        for (int nt = 0; nt < 4; nt++) {
            int c = wn * 32 + nt * 8 + (lane & 3) * 2;
            #pragma unroll
            for (int rr = 0; rr < 2; rr++) {
                int r  = wm * 64 + mt * 16 + (lane >> 2) + rr * 8;
                int gm = m0 + r;
                if (gm < cnt) {
                    size_t dst = (size_t)(base + gm) * DIM_ + n0 + c;
                    *(float2*)(g_y + dst) = make_float2(acc[mt][nt][2*rr], acc[mt][nt][2*rr+1]);
                }
            }
        }
}

// ---------------------------------------------------------------------------
// Combine
// ---------------------------------------------------------------------------
__global__ void combine_kernel(float* __restrict__ out) {
    const int t  = blockIdx.x;
    const int e0 = g_eid[t][0];
    const int e1 = g_eid[t][1];
    const int n0 = g_off[e0] + g_pos[t][0];
    const int n1 = g_off[e1] + g_pos[t][1];
    const float w0 = g_ew[t][0];
    const float w1 = g_ew[t][1];
    const float* y0 = &g_y[(size_t)n0 * DIM_];
    const float* y1 = &g_y[(size_t)n1 * DIM_];
    float* op = out + (size_t)t * DIM_;
    for (int d = threadIdx.x * 4; d < DIM_; d += blockDim.x * 4) {
        float4 a = *(const float4*)(y0 + d);
        float4 b = *(const float4*)(y1 + d);
        *(float4*)(op + d) = make_float4(w0 * a.x + w1 * b.x, w0 * a.y + w1 * b.y,
                                         w0 * a.z + w1 * b.z, w0 * a.w + w1 * b.w);
    }
}

// ---------------------------------------------------------------------------
// Entry point
// ---------------------------------------------------------------------------
extern "C" void kernel_launch(void* const* d_in, const int* in_sizes, int n_in,
                              void* d_out, int out_size) {
    const float* x  = (const float*)d_in[0];
    const float* gw = (const float*)d_in[1];
    const float* w1 = (const float*)d_in[2];
    const float* w2 = (const float*)d_in[3];
    const float* w3 = (const float*)d_in[4];
    float* out = (float*)d_out;

    cudaFuncSetAttribute(ffn1_kernel, cudaFuncAttributeMaxDynamicSharedMemorySize, SMEM_TOT);
    cudaFuncSetAttribute(ffn2_kernel, cudaFuncAttributeMaxDynamicSharedMemorySize, SMEM_TOT);

    gate_kernel<<<T_TOKENS, 256>>>(x, gw);
    route_kernel<<<1, 256>>>();
    cvt_x_kernel<<<(T_TOKENS * DIM_ / 4) / 256, 256>>>(x);
    ffn1_kernel<<<dim3(T_TOKENS / 128, HID_ / 64, NEXP), 256, SMEM_TOT>>>(w1, w3);
    ffn2_kernel<<<dim3(T_TOKENS / 128, DIM_ / 128, NEXP), 256, SMEM_TOT>>>(w2);
    combine_kernel<<<T_TOKENS, 256>>>(out);
}

// round 17
// speedup vs baseline: 6.0795x; 1.2167x over previous
#include <cuda_runtime.h>
#include <cuda_fp16.h>
#include <cstdint>

#define T_TOKENS 2048
#define DIM_     2048
#define HID_     5632
#define NEXP     8
#define NENT     (T_TOKENS * 2)

// ---------------------------------------------------------------------------
// Scratch (device globals — no cudaMalloc allowed)
// ---------------------------------------------------------------------------
__device__ int   g_eid [T_TOKENS][2];
__device__ float g_ew  [T_TOKENS][2];
__device__ int   g_pos [T_TOKENS][2];
__device__ int   g_list[NEXP][T_TOKENS];
__device__ int   g_cnt [NEXP];
__device__ int   g_off [NEXP];
__device__ __half g_xh[(size_t)T_TOKENS * DIM_];   // fp16 x
__device__ __half g_hh[(size_t)NENT * HID_];       // fp16 h
__device__ float  g_y [(size_t)NENT * DIM_];

// ---------------------------------------------------------------------------
// Helpers
// ---------------------------------------------------------------------------
__device__ __forceinline__ uint32_t smem_u32(const void* p) {
    uint32_t a;
    asm("{ .reg .u64 t; cvta.to.shared.u64 t, %1; cvt.u32.u64 %0, t; }" : "=r"(a) : "l"(p));
    return a;
}
__device__ __forceinline__ uint32_t pack_h(float f0, float f1) {
    return (uint32_t)__half_as_ushort(__float2half_rn(f0))
         | ((uint32_t)__half_as_ushort(__float2half_rn(f1)) << 16);
}

#define LDM_X4(r, addr)                                                          \
    asm volatile("ldmatrix.sync.aligned.m8n8.x4.shared.b16 {%0,%1,%2,%3}, [%4];" \
        : "=r"((r)[0]), "=r"((r)[1]), "=r"((r)[2]), "=r"((r)[3]) : "r"(addr))

#define MMA_F16(d, a, b0, b1)                                                    \
    asm volatile("mma.sync.aligned.m16n8k16.row.col.f32.f16.f16.f32 "            \
        "{%0,%1,%2,%3}, {%4,%5,%6,%7}, {%8,%9}, {%0,%1,%2,%3};"                  \
        : "+f"((d)[0]), "+f"((d)[1]), "+f"((d)[2]), "+f"((d)[3])                 \
        : "r"((a)[0]), "r"((a)[1]), "r"((a)[2]), "r"((a)[3]), "r"(b0), "r"(b1))

#define CP_ASYNC16(dst, src)                                                     \
    asm volatile("cp.async.cg.shared.global [%0], [%1], 16;" :: "r"(dst), "l"(src))
#define CP_COMMIT() asm volatile("cp.async.commit_group;" ::: "memory")
#define CP_WAIT0()  asm volatile("cp.async.wait_group 0;" ::: "memory")

// Smem: rows of 32 fp16 padded to 80B -> conflict-free ldmatrix (proven R4-R16)
// 4 buffers of BK=32 organized as 2 pairs; one barrier per pair (64-k).
#define ROWB     80
#define TILE_A   10240          // 128 rows * 80B
#define OFF_A    0
#define OFF_B    10240          // B: single fp16 matrix, 128 rows * 80B
#define BUF_B    20480
#define SMEM_TOT (4 * BUF_B)    // 81920; 2 CTAs/SM

// ---------------------------------------------------------------------------
// Gating + routing + x convert (gate stays full fp32 — routing must be exact)
// ---------------------------------------------------------------------------
__global__ void gate_kernel(const float* __restrict__ x, const float* __restrict__ gw) {
    const int t = blockIdx.x, lane = threadIdx.x & 31, w = threadIdx.x >> 5;
    const float* xr = x + (size_t)t * DIM_;
    const float* gr = gw + (size_t)w * DIM_;
    float s = 0.f;
    for (int d = lane * 4; d < DIM_; d += 128) {
        float4 a = *(const float4*)(xr + d);
        float4 b = *(const float4*)(gr + d);
        s += a.x * b.x + a.y * b.y + a.z * b.z + a.w * b.w;
    }
    #pragma unroll
    for (int o = 16; o; o >>= 1) s += __shfl_xor_sync(0xffffffffu, s, o);
    __shared__ float sc[NEXP];
    if (lane == 0) sc[w] = s;
    __syncthreads();
    if (threadIdx.x == 0) {
        int b0 = 0; float s0 = sc[0];
        #pragma unroll
        for (int e = 1; e < NEXP; e++) if (sc[e] > s0) { s0 = sc[e]; b0 = e; }
        int b1 = -1; float s1 = -1e30f;
        #pragma unroll
        for (int e = 0; e < NEXP; e++) if (e != b0 && sc[e] > s1) { s1 = sc[e]; b1 = e; }
        float e1 = __expf(s1 - s0);
        float inv = 1.f / (1.f + e1);
        g_eid[t][0] = b0; g_eid[t][1] = b1;
        g_ew [t][0] = inv; g_ew [t][1] = e1 * inv;
    }
}

__global__ void route_kernel() {
    const int lane = threadIdx.x & 31, e = threadIdx.x >> 5;
    if (e < NEXP) {
        int cnt = 0;
        for (int t0 = 0; t0 < T_TOKENS; t0 += 32) {
            int t = t0 + lane;
            int e0 = g_eid[t][0], e1 = g_eid[t][1];
            bool sel = (e0 == e) || (e1 == e);
            int slot = (e0 == e) ? 0 : 1;
            unsigned m = __ballot_sync(0xffffffffu, sel);
            if (sel) {
                int p = cnt + __popc(m & ((1u << lane) - 1u));
                g_list[e][p] = t;
                g_pos[t][slot] = p;
            }
            cnt += __popc(m);
        }
        if (lane == 0) g_cnt[e] = cnt;
    }
    __syncthreads();
    if (threadIdx.x == 0) {
        int off = 0;
        #pragma unroll
        for (int i = 0; i < NEXP; i++) { g_off[i] = off; off += g_cnt[i]; }
    }
}

__global__ void cvt_x_kernel(const float* __restrict__ x) {
    int i = blockIdx.x * blockDim.x + threadIdx.x;
    float4 v = ((const float4*)x)[i];
    size_t o = (size_t)i * 4;
    g_xh[o + 0] = __float2half_rn(v.x);
    g_xh[o + 1] = __float2half_rn(v.y);
    g_xh[o + 2] = __float2half_rn(v.z);
    g_xh[o + 3] = __float2half_rn(v.w);
}

// ---------------------------------------------------------------------------
// GEMM1: u = x@w1, v = x@w3.  A = fp16 x; B = fp16 (w1/w3 interleaved rows).
// 256 threads (2m x 4n warps, warp tile 64x32), CTA 128 tokens x 64 h-cols.
// 4 buffers (2 pairs), BK=64 per barrier.
// ---------------------------------------------------------------------------
__global__ void __launch_bounds__(256, 2) ffn1_kernel(const float* __restrict__ w1,
                                                      const float* __restrict__ w3) {
    const int e   = blockIdx.z;
    const int cnt = g_cnt[e];
    const int m0  = blockIdx.x * 128;
    if (m0 >= cnt) return;
    const int n0   = blockIdx.y * 64;     // h-cols
    const int base = g_off[e];

    extern __shared__ char sm[];
    const uint32_t sbase = smem_u32(sm);
    const int tid = threadIdx.x, lane = tid & 31, wid = tid >> 5;
    const int wm = wid & 1, wn = wid >> 1;

    const float* w1e = w1 + (size_t)e * DIM_ * HID_;
    const float* w3e = w3 + (size_t)e * DIM_ * HID_;

    // A loader: per buffer 512 chunks (128 rows x 4 kq), 2/thread
    const __half* apA[2];
    uint32_t aoA[2];
    #pragma unroll
    for (int q = 0; q < 2; q++) {
        int idx = tid + q * 256;
        int row = idx >> 2, kq = idx & 3;
        int tok = g_list[e][min(m0 + row, cnt - 1)];
        apA[q] = g_xh + (size_t)tok * DIM_ + kq * 8;
        aoA[q] = row * ROWB + kq * 16;
    }
    // B loader: per buffer 512 tasks (128 interleaved rows x 4 k-blocks), 2/thread
    int bnT[2], bkT[2];
    const float* pB[2];
    #pragma unroll
    for (int r = 0; r < 2; r++) {
        int task = tid + r * 256;
        bnT[r] = task & 127;
        bkT[r] = task >> 7;
        pB[r]  = ((bnT[r] & 1) ? w3e : w1e) + (size_t)(bkT[r] * 8) * HID_ + (n0 + (bnT[r] >> 1));
    }

    const int mi = lane >> 3, lr = lane & 7;
    const uint32_t aLB = (uint32_t)((wm * 64 + (mi & 1) * 8 + lr) * ROWB + (mi >> 1) * 16);
    const uint32_t bLB = (uint32_t)((wn * 32 + (mi >> 1) * 8 + lr) * ROWB + (mi & 1) * 16);

    float acc[4][4][4];
    #pragma unroll
    for (int a = 0; a < 4; a++)
        #pragma unroll
        for (int b = 0; b < 4; b++)
            #pragma unroll
            for (int c = 0; c < 4; c++) acc[a][b][c] = 0.f;

    // fill one BK=32 buffer (A via cp.async, B via LDG+convert+STS)
    auto fill_buf = [&](int buf, int kk) {
        const uint32_t bs = sbase + buf * BUF_B;
        char* bc = sm + buf * BUF_B;
        #pragma unroll
        for (int q = 0; q < 2; q++) CP_ASYNC16(bs + OFF_A + aoA[q], apA[q] + kk);
        #pragma unroll
        for (int r = 0; r < 2; r++) {
            float f[8];
            #pragma unroll
            for (int j = 0; j < 8; j++) f[j] = pB[r][(size_t)(kk + j) * HID_];
            uint32_t bo = bnT[r] * ROWB + bkT[r] * 16;
            *(uint4*)(bc + OFF_B + bo) = make_uint4(pack_h(f[0], f[1]), pack_h(f[2], f[3]),
                                                    pack_h(f[4], f[5]), pack_h(f[6], f[7]));
        }
    };
    auto comp_buf = [&](int buf) {
        const uint32_t bs = sbase + buf * BUF_B;
        #pragma unroll
        for (int ks = 0; ks < 2; ks++) {
            uint32_t bh[2][4];
            #pragma unroll
            for (int ng = 0; ng < 2; ng++)
                LDM_X4(bh[ng], bs + OFF_B + bLB + ng * (16 * ROWB) + ks * 32);
            #pragma unroll
            for (int mt = 0; mt < 4; mt++) {
                uint32_t ah[4];
                LDM_X4(ah, bs + OFF_A + aLB + mt * (16 * ROWB) + ks * 32);
                #pragma unroll
                for (int ng = 0; ng < 2; ng++)
                    #pragma unroll
                    for (int h2 = 0; h2 < 2; h2++)
                        MMA_F16(acc[mt][ng*2+h2], ah, bh[ng][2*h2], bh[ng][2*h2+1]);
            }
        }
    };

    const int NP = DIM_ / 64;   // 32 pair-iterations
    // prologue: pair 0 (buffers 0,1 = chunks 0,1)
    fill_buf(0, 0);
    fill_buf(1, 32);
    CP_COMMIT();
    CP_WAIT0();
    __syncthreads();

    for (int i = 0; i < NP; i++) {
        const int s = i & 1;
        if (i + 1 < NP) {
            int kk = (i + 1) * 64;
            fill_buf((1 - s) * 2,     kk);
            fill_buf((1 - s) * 2 + 1, kk + 32);
            CP_COMMIT();
        }
        comp_buf(s * 2);
        comp_buf(s * 2 + 1);
        CP_WAIT0();
        __syncthreads();
    }

    // epilogue: d0=u, d1=v for the same h-col, in-register SwiGLU
    #pragma unroll
    for (int mt = 0; mt < 4; mt++)
        #pragma unroll
        for (int nt = 0; nt < 4; nt++) {
            int j = wn * 16 + nt * 4 + (lane & 3);
            #pragma unroll
            for (int rr = 0; rr < 2; rr++) {
                int r  = wm * 64 + mt * 16 + (lane >> 2) + rr * 8;
                int gm = m0 + r;
                float u = acc[mt][nt][2*rr], v = acc[mt][nt][2*rr+1];
                float h = u / (1.f + __expf(-u)) * v;
                if (gm < cnt) {
                    size_t dst = (size_t)(base + gm) * HID_ + n0 + j;
                    g_hh[dst] = __float2half_rn(h);
                }
            }
        }
}

// ---------------------------------------------------------------------------
// GEMM2: y = h @ w2.  A = fp16 h; B = fp16 w2.  CTA 128 x 128, BK=64/barrier.
// ---------------------------------------------------------------------------
__global__ void __launch_bounds__(256, 2) ffn2_kernel(const float* __restrict__ w2) {
    const int e   = blockIdx.z;
    const int cnt = g_cnt[e];
    const int m0  = blockIdx.x * 128;
    if (m0 >= cnt) return;
    const int n0   = blockIdx.y * 128;
    const int base = g_off[e];

    extern __shared__ char sm[];
    const uint32_t sbase = smem_u32(sm);
    const int tid = threadIdx.x, lane = tid & 31, wid = tid >> 5;
    const int wm = wid & 1, wn = wid >> 1;

    const float* w2e = w2 + (size_t)e * HID_ * DIM_;

    const __half* apA[2];
    uint32_t aoA[2];
    #pragma unroll
    for (int q = 0; q < 2; q++) {
        int idx = tid + q * 256;
        int row = idx >> 2, kq = idx & 3;
        int r   = base + min(m0 + row, cnt - 1);
        apA[q] = g_hh + (size_t)r * HID_ + kq * 8;
        aoA[q] = row * ROWB + kq * 16;
    }
    int bnT[2], bkT[2];
    const float* pB[2];
    #pragma unroll
    for (int r = 0; r < 2; r++) {
        int task = tid + r * 256;
        bnT[r] = task & 127;
        bkT[r] = task >> 7;
        pB[r]  = w2e + (size_t)(bkT[r] * 8) * DIM_ + (n0 + bnT[r]);
    }

    const int mi = lane >> 3, lr = lane & 7;
    const uint32_t aLB = (uint32_t)((wm * 64 + (mi & 1) * 8 + lr) * ROWB + (mi >> 1) * 16);
    const uint32_t bLB = (uint32_t)((wn * 32 + (mi >> 1) * 8 + lr) * ROWB + (mi & 1) * 16);

    float acc[4][4][4];
    #pragma unroll
    for (int a = 0; a < 4; a++)
        #pragma unroll
        for (int b = 0; b < 4; b++)
            #pragma unroll
            for (int c = 0; c < 4; c++) acc[a][b][c] = 0.f;

    auto fill_buf = [&](int buf, int kk) {
        const uint32_t bs = sbase + buf * BUF_B;
        char* bc = sm + buf * BUF_B;
        #pragma unroll
        for (int q = 0; q < 2; q++) CP_ASYNC16(bs + OFF_A + aoA[q], apA[q] + kk);
        #pragma unroll
        for (int r = 0; r < 2; r++) {
            float f[8];
            #pragma unroll
            for (int j = 0; j < 8; j++) f[j] = pB[r][(size_t)(kk + j) * DIM_];
            uint32_t bo = bnT[r] * ROWB + bkT[r] * 16;
            *(uint4*)(bc + OFF_B + bo) = make_uint4(pack_h(f[0], f[1]), pack_h(f[2], f[3]),
                                                    pack_h(f[4], f[5]), pack_h(f[6], f[7]));
        }
    };
    auto comp_buf = [&](int buf) {
        const uint32_t bs = sbase + buf * BUF_B;
        #pragma unroll
        for (int ks = 0; ks < 2; ks++) {
            uint32_t bh[2][4];
            #pragma unroll
            for (int ng = 0; ng < 2; ng++)
                LDM_X4(bh[ng], bs + OFF_B + bLB + ng * (16 * ROWB) + ks * 32);
            #pragma unroll
            for (int mt = 0; mt < 4; mt++) {
                uint32_t ah[4];
                LDM_X4(ah, bs + OFF_A + aLB + mt * (16 * ROWB) + ks * 32);
                #pragma unroll
                for (int ng = 0; ng < 2; ng++)
                    #pragma unroll
                    for (int h2 = 0; h2 < 2; h2++)
                        MMA_F16(acc[mt][ng*2+h2], ah, bh[ng][2*h2], bh[ng][2*h2+1]);
            }
        }
    };

    const int NP = HID_ / 64;   // 88 pair-iterations
    fill_buf(0, 0);
    fill_buf(1, 32);
    CP_COMMIT();
    CP_WAIT0();
    __syncthreads();

    for (int i = 0; i < NP; i++) {
        const int s = i & 1;
        if (i + 1 < NP) {
            int kk = (i + 1) * 64;
            fill_buf((1 - s) * 2,     kk);
            fill_buf((1 - s) * 2 + 1, kk + 32);
            CP_COMMIT();
        }
        comp_buf(s * 2);
        comp_buf(s * 2 + 1);
        CP_WAIT0();
        __syncthreads();
    }

    #pragma unroll
    for (int mt = 0; mt < 4; mt++)
        #pragma unroll
        for (int nt = 0; nt < 4; nt++) {
            int c = wn * 32 + nt * 8 + (lane & 3) * 2;
            #pragma unroll
            for (int rr = 0; rr < 2; rr++) {
                int r  = wm * 64 + mt * 16 + (lane >> 2) + rr * 8;
                int gm = m0 + r;
                if (gm < cnt) {
                    size_t dst = (size_t)(base + gm) * DIM_ + n0 + c;
                    *(float2*)(g_y + dst) = make_float2(acc[mt][nt][2*rr], acc[mt][nt][2*rr+1]);
                }
            }
        }
}

// ---------------------------------------------------------------------------
// Combine
// ---------------------------------------------------------------------------
__global__ void combine_kernel(float* __restrict__ out) {
    const int t  = blockIdx.x;
    const int e0 = g_eid[t][0];
    const int e1 = g_eid[t][1];
    const int n0 = g_off[e0] + g_pos[t][0];
    const int n1 = g_off[e1] + g_pos[t][1];
    const float w0 = g_ew[t][0];
    const float w1 = g_ew[t][1];
    const float* y0 = &g_y[(size_t)n0 * DIM_];
    const float* y1 = &g_y[(size_t)n1 * DIM_];
    float* op = out + (size_t)t * DIM_;
    for (int d = threadIdx.x * 4; d < DIM_; d += blockDim.x * 4) {
        float4 a = *(const float4*)(y0 + d);
        float4 b = *(const float4*)(y1 + d);
        *(float4*)(op + d) = make_float4(w0 * a.x + w1 * b.x, w0 * a.y + w1 * b.y,
                                         w0 * a.z + w1 * b.z, w0 * a.w + w1 * b.w);
    }
}

// ---------------------------------------------------------------------------
// Entry point
// ---------------------------------------------------------------------------
extern "C" void kernel_launch(void* const* d_in, const int* in_sizes, int n_in,
                              void* d_out, int out_size) {
    const float* x  = (const float*)d_in[0];
    const float* gw = (const float*)d_in[1];
    const float* w1 = (const float*)d_in[2];
    const float* w2 = (const float*)d_in[3];
    const float* w3 = (const float*)d_in[4];
    float* out = (float*)d_out;

    cudaFuncSetAttribute(ffn1_kernel, cudaFuncAttributeMaxDynamicSharedMemorySize, SMEM_TOT);
    cudaFuncSetAttribute(ffn2_kernel, cudaFuncAttributeMaxDynamicSharedMemorySize, SMEM_TOT);

    gate_kernel<<<T_TOKENS, 256>>>(x, gw);
    route_kernel<<<1, 256>>>();
    cvt_x_kernel<<<(T_TOKENS * DIM_ / 4) / 256, 256>>>(x);
    ffn1_kernel<<<dim3(T_TOKENS / 128, HID_ / 64, NEXP), 256, SMEM_TOT>>>(w1, w3);
    ffn2_kernel<<<dim3(T_TOKENS / 128, DIM_ / 128, NEXP), 256, SMEM_TOT>>>(w2);
    combine_kernel<<<T_TOKENS, 256>>>(out);
}